// round 1
// baseline (speedup 1.0000x reference)
#include <cuda_runtime.h>

// ---------------- constants ----------------
#define NMAX   100000
#define CIN    64
#define CMID   32
#define KN     16
#define WNOUT  16
#define COUT   128

// ---------------- scratch (device globals: sanctioned workaround) ----------------
__device__ float g_feats32[NMAX * CMID];                 // 12.8 MB
__device__ float g_agg[(size_t)NMAX * 1024];             // 409.6 MB
__device__ float g_x[(size_t)NMAX * 64];                 // 25.6 MB

__device__ __forceinline__ float lrelu(float v) { return v > 0.f ? v : 0.1f * v; }

// packed f32x2 helpers (sm_103a)
#define FMA2(d, a, b, c) \
    asm("fma.rn.f32x2 %0, %1, %2, %3;" : "=l"(d) : "l"(a), "l"(b), "l"(c))

__device__ __forceinline__ unsigned long long pack2(float lo, float hi) {
    unsigned long long r;
    asm("mov.b64 %0, {%1, %2};" : "=l"(r) : "f"(lo), "f"(hi));
    return r;
}
__device__ __forceinline__ void unpack2(unsigned long long v, float& lo, float& hi) {
    asm("mov.b64 {%0, %1}, %2;" : "=f"(lo), "=f"(hi) : "l"(v));
}

// ============================================================================
// K1: feats32[n][c] = dense_feats[n] @ u1_w + u1_b   (no activation)
// 128 threads, 4 points/block
// ============================================================================
__global__ __launch_bounds__(128) void k1_unary1(
    const float* __restrict__ feats, const float* __restrict__ u1w,
    const float* __restrict__ u1b, int N)
{
    __shared__ float su[CIN * CMID];   // 8 KB
    __shared__ float sf[4 * CIN];
    int t = threadIdx.x;
    int p0 = blockIdx.x * 4;
    for (int i = t; i < CIN * CMID; i += 128) su[i] = u1w[i];
#pragma unroll
    for (int q = 0; q < 2; q++) {
        int idx = q * 128 + t;
        int pl = idx >> 6, i = idx & 63;
        int p = p0 + pl;
        sf[idx] = (p < N) ? feats[p * CIN + i] : 0.f;
    }
    __syncthreads();
    int pl = t >> 5, c = t & 31;
    int p = p0 + pl;
    float acc = u1b[c];
#pragma unroll
    for (int i = 0; i < CIN; i++) acc += sf[pl * CIN + i] * su[i * CMID + c];
    if (p < N) g_feats32[p * CMID + c] = acc;
}

// ============================================================================
// K2: per-point: localized (2nd output), pe MLP, weightnet, gather, agg
// 1 point per 128-thread block
// ============================================================================
__global__ __launch_bounds__(128) void k2_point(
    const float* __restrict__ xyz, const int* __restrict__ nei,
    const float* __restrict__ pw1, const float* __restrict__ pb1,
    const float* __restrict__ pw2, const float* __restrict__ pb2,
    const float* __restrict__ ww1, const float* __restrict__ wb1,
    const float* __restrict__ ww2, const float* __restrict__ wb2,
    const float* __restrict__ ww3, const float* __restrict__ wb3,
    float* __restrict__ loc_out, int N, int writeLoc)
{
    __shared__ float s_pw1[96], s_pb1[32];
    __shared__ float s_pw2[1024], s_pb2[32];
    __shared__ float s_ww1[24], s_wb1[8], s_ww2[64], s_wb2[8], s_ww3[128], s_wb3[16];
    __shared__ float s_loc[48];
    __shared__ __align__(16) float s_ph[512];   // transposed: [h][16]
    __shared__ float s_pe[512];                 // [k][32]
    __shared__ float s_gf[512];                 // [k][32]
    __shared__ float s_wh1[128], s_wh2[128];
    __shared__ __align__(16) float s_w[256];    // [k][16]
    __shared__ int   s_nei[16];
    __shared__ float s_ctr[3];

    int n = blockIdx.x;
    int t = threadIdx.x;

    // ---- load small weights + point meta ----
    s_pw1[t % 96] = pw1[t % 96];            // covers 96 with 128 threads (dup harmless)
    if (t < 32) { s_pb1[t] = pb1[t]; s_pb2[t] = pb2[t]; }
    for (int i = t; i < 1024; i += 128) s_pw2[i] = pw2[i];
    if (t < 24) s_ww1[t] = ww1[t];
    if (t < 8)  s_wb1[t] = wb1[t];
    if (t < 64) s_ww2[t] = ww2[t];
    if (t >= 64 && t < 72) s_wb2[t - 64] = wb2[t - 64];
    s_ww3[t] = ww3[t];                      // exactly 128
    if (t < 16) { s_wb3[t] = wb3[t]; s_nei[t] = nei[n * KN + t]; }
    if (t >= 16 && t < 19) s_ctr[t - 16] = xyz[n * 3 + (t - 16)];
    __syncthreads();

    // ---- localized + gather feats32 ----
    if (t < 48) {
        int k = t / 3, d = t - k * 3;
        float v = xyz[s_nei[k] * 3 + d] - s_ctr[d];
        s_loc[t] = v;
        if (writeLoc) loc_out[(size_t)n * 48 + t] = v;
    }
#pragma unroll
    for (int q = 0; q < 4; q++) {
        int idx = q * 128 + t;
        int k = idx >> 5, c = idx & 31;
        s_gf[idx] = g_feats32[s_nei[k] * CMID + c];
    }
    __syncthreads();

    // ---- pe hidden (store transposed [h][k]) + wn hidden1 ----
    {
        int k = t & 15, hb = t >> 4;    // hb 0..7
        float l0 = s_loc[k * 3 + 0], l1 = s_loc[k * 3 + 1], l2 = s_loc[k * 3 + 2];
#pragma unroll
        for (int q = 0; q < 4; q++) {
            int h = hb + q * 8;
            float a = s_pb1[h] + l0 * s_pw1[h] + l1 * s_pw1[32 + h] + l2 * s_pw1[64 + h];
            s_ph[h * 16 + k] = lrelu(a);
        }
        int kk = t >> 3, hh = t & 7;
        float m0 = s_loc[kk * 3], m1 = s_loc[kk * 3 + 1], m2 = s_loc[kk * 3 + 2];
        float a = s_wb1[hh] + m0 * s_ww1[hh] + m1 * s_ww1[8 + hh] + m2 * s_ww1[16 + hh];
        s_wh1[kk * 8 + hh] = lrelu(a);
    }
    __syncthreads();

    // ---- pe out + wn hidden2 (no act) ----
    {
        int c = t & 31, kb = (t >> 5) * 4;
        float a0 = s_pb2[c], a1 = a0, a2 = a0, a3 = a0;
#pragma unroll
        for (int h = 0; h < 32; h++) {
            float4 p4 = *(const float4*)&s_ph[h * 16 + kb];   // broadcast per warp
            float w2 = s_pw2[h * 32 + c];                      // coalesced
            a0 += p4.x * w2; a1 += p4.y * w2; a2 += p4.z * w2; a3 += p4.w * w2;
        }
        s_pe[(kb + 0) * 32 + c] = lrelu(a0);
        s_pe[(kb + 1) * 32 + c] = lrelu(a1);
        s_pe[(kb + 2) * 32 + c] = lrelu(a2);
        s_pe[(kb + 3) * 32 + c] = lrelu(a3);

        int kk = t >> 3, hh = t & 7;
        float a = s_wb2[hh];
#pragma unroll
        for (int j = 0; j < 8; j++) a += s_wh1[kk * 8 + j] * s_ww2[j * 8 + hh];
        s_wh2[kk * 8 + hh] = a;   // no activation
    }
    __syncthreads();

    // ---- wn final ----
#pragma unroll
    for (int q = 0; q < 2; q++) {
        int idx = q * 128 + t;
        int k = idx >> 4, wo = idx & 15;
        float a = s_wb3[wo];
#pragma unroll
        for (int j = 0; j < 8; j++) a += s_wh2[k * 8 + j] * s_ww3[j * 16 + wo];
        s_w[idx] = lrelu(a);
    }
    __syncthreads();

    // ---- agg[c][w] = sum_k nf[k][c]*w[k][w];  thread: fixed c, 8 w's ----
    {
        int half = t >> 6, c = t & 63, w0 = half * 8;
        float acc[8];
#pragma unroll
        for (int j = 0; j < 8; j++) acc[j] = 0.f;
        const float* src = (c < 32) ? &s_gf[c] : &s_pe[c - 32];
#pragma unroll
        for (int k = 0; k < KN; k++) {
            float sv = src[k * 32];
            float4 wa = *(const float4*)&s_w[k * 16 + w0];
            float4 wb = *(const float4*)&s_w[k * 16 + w0 + 4];
            acc[0] += sv * wa.x; acc[1] += sv * wa.y; acc[2] += sv * wa.z; acc[3] += sv * wa.w;
            acc[4] += sv * wb.x; acc[5] += sv * wb.y; acc[6] += sv * wb.z; acc[7] += sv * wb.w;
        }
        float* dst = &g_agg[(size_t)n * 1024 + c * 16 + w0];
        *(float4*)dst       = make_float4(acc[0], acc[1], acc[2], acc[3]);
        *(float4*)(dst + 4) = make_float4(acc[4], acc[5], acc[6], acc[7]);
    }
}

// ============================================================================
// K3: x = leaky(agg @ lin_w + lin_b)  — (N x 1024)@(1024 x 64), f32x2 FMA
// 64-row tile, full 64 cols, K-tile 32. 256 threads, thread tile 4x4.
// A stored SPLAT in smem (each value duplicated) so FMA2 needs no packs.
// ============================================================================
__global__ __launch_bounds__(256) void k3_lin(
    const float* __restrict__ lw, const float* __restrict__ lb, int N)
{
    __shared__ __align__(16) float As[32 * 130];   // [k][2*row], pad 130
    __shared__ __align__(16) float Ws[32 * 64];    // [k][c]
    int t  = threadIdx.x;
    int tb = blockIdx.x * 64;
    int tx = t & 15, ty = t >> 4;
    int j  = tx * 4;

    unsigned long long acc[4][2];
#pragma unroll
    for (int r = 0; r < 4; r++) { acc[r][0] = 0ull; acc[r][1] = 0ull; }

    for (int kt = 0; kt < 32; kt++) {
        int kb = kt * 32;
        __syncthreads();
        // load A tile (64 rows x 32 k), splat-store transposed
        {
            int row = t >> 2, l4 = t & 3;
            int grow = tb + row; if (grow >= N) grow = N - 1;
            const float4* ap = (const float4*)&g_agg[(size_t)grow * 1024 + kb + l4 * 8];
            float4 a0 = ap[0], a1 = ap[1];
            int kk = l4 * 8;
            *(unsigned long long*)&As[(kk + 0) * 130 + 2 * row] = pack2(a0.x, a0.x);
            *(unsigned long long*)&As[(kk + 1) * 130 + 2 * row] = pack2(a0.y, a0.y);
            *(unsigned long long*)&As[(kk + 2) * 130 + 2 * row] = pack2(a0.z, a0.z);
            *(unsigned long long*)&As[(kk + 3) * 130 + 2 * row] = pack2(a0.w, a0.w);
            *(unsigned long long*)&As[(kk + 4) * 130 + 2 * row] = pack2(a1.x, a1.x);
            *(unsigned long long*)&As[(kk + 5) * 130 + 2 * row] = pack2(a1.y, a1.y);
            *(unsigned long long*)&As[(kk + 6) * 130 + 2 * row] = pack2(a1.z, a1.z);
            *(unsigned long long*)&As[(kk + 7) * 130 + 2 * row] = pack2(a1.w, a1.w);
        }
        // load W tile (32 k x 64 c)
#pragma unroll
        for (int q = 0; q < 2; q++) {
            int f4 = q * 256 + t;
            int kk = f4 >> 4, c4 = (f4 & 15) * 4;
            *(float4*)&Ws[kk * 64 + c4] = *(const float4*)&lw[(size_t)(kb + kk) * 64 + c4];
        }
        __syncthreads();
#pragma unroll
        for (int k = 0; k < 32; k++) {
            unsigned long long a0 = *(const unsigned long long*)&As[k * 130 + 2 * (ty * 4 + 0)];
            unsigned long long a1 = *(const unsigned long long*)&As[k * 130 + 2 * (ty * 4 + 1)];
            unsigned long long a2 = *(const unsigned long long*)&As[k * 130 + 2 * (ty * 4 + 2)];
            unsigned long long a3 = *(const unsigned long long*)&As[k * 130 + 2 * (ty * 4 + 3)];
            ulonglong2 wv = *(const ulonglong2*)&Ws[k * 64 + j];
            FMA2(acc[0][0], a0, wv.x, acc[0][0]); FMA2(acc[0][1], a0, wv.y, acc[0][1]);
            FMA2(acc[1][0], a1, wv.x, acc[1][0]); FMA2(acc[1][1], a1, wv.y, acc[1][1]);
            FMA2(acc[2][0], a2, wv.x, acc[2][0]); FMA2(acc[2][1], a2, wv.y, acc[2][1]);
            FMA2(acc[3][0], a3, wv.x, acc[3][0]); FMA2(acc[3][1], a3, wv.y, acc[3][1]);
        }
    }
    float b0 = lb[j], b1 = lb[j + 1], b2 = lb[j + 2], b3 = lb[j + 3];
#pragma unroll
    for (int r = 0; r < 4; r++) {
        int row = tb + ty * 4 + r;
        if (row < N) {
            float x0, x1, x2, x3;
            unpack2(acc[r][0], x0, x1);
            unpack2(acc[r][1], x2, x3);
            *(float4*)&g_x[(size_t)row * 64 + j] =
                make_float4(lrelu(x0 + b0), lrelu(x1 + b1), lrelu(x2 + b2), lrelu(x3 + b3));
        }
    }
}

// ============================================================================
// K4: out = leaky(x @ u2_w + u2_b + feats @ sc_w + sc_b)
// 32 points/block, 256 threads, f32x2. Dynamic smem ~96.5 KB.
// smem: su2[8192] ssc[8192] xs2[4096] fs2[4096] sb[128]  (floats)
// ============================================================================
__global__ __launch_bounds__(256) void k4_final(
    const float* __restrict__ feats, const float* __restrict__ u2w,
    const float* __restrict__ u2b, const float* __restrict__ scw,
    const float* __restrict__ scb, float* __restrict__ out, int N)
{
    extern __shared__ __align__(16) float smem[];
    float* su2 = smem;            // 64*128
    float* ssc = su2 + 8192;      // 64*128
    float* xs2 = ssc + 8192;      // 32*128 (splat pairs)
    float* fs2 = xs2 + 4096;      // 32*128 (splat pairs)
    float* sb  = fs2 + 4096;      // 128

    int t = threadIdx.x;
    int p0 = blockIdx.x * 32;
#pragma unroll
    for (int q = 0; q < 8; q++) {
        int f4 = q * 256 + t;
        *(float4*)&su2[f4 * 4] = *(const float4*)&u2w[f4 * 4];
        *(float4*)&ssc[f4 * 4] = *(const float4*)&scw[f4 * 4];
    }
    if (t < 128) sb[t] = u2b[t] + scb[t];
#pragma unroll
    for (int q = 0; q < 8; q++) {
        int idx = q * 256 + t;
        int pl = idx >> 6, i = idx & 63;
        int p = p0 + pl;
        float v = (p < N) ? g_x[(size_t)p * 64 + i] : 0.f;
        float f = (p < N) ? feats[(size_t)p * 64 + i] : 0.f;
        *(unsigned long long*)&xs2[pl * 128 + 2 * i] = pack2(v, v);
        *(unsigned long long*)&fs2[pl * 128 + 2 * i] = pack2(f, f);
    }
    __syncthreads();

    int j = (t & 31) * 4, rg = t >> 5;
#pragma unroll
    for (int rr = 0; rr < 4; rr++) {
        int r = rg * 4 + rr;
        int p = p0 + r;
        unsigned long long acc0 = *(const unsigned long long*)&sb[j];
        unsigned long long acc1 = *(const unsigned long long*)&sb[j + 2];
#pragma unroll 8
        for (int jj = 0; jj < 64; jj++) {
            unsigned long long xv = *(const unsigned long long*)&xs2[r * 128 + 2 * jj];
            ulonglong2 wv = *(const ulonglong2*)&su2[jj * 128 + j];
            FMA2(acc0, xv, wv.x, acc0);
            FMA2(acc1, xv, wv.y, acc1);
        }
#pragma unroll 8
        for (int i = 0; i < 64; i++) {
            unsigned long long fv = *(const unsigned long long*)&fs2[r * 128 + 2 * i];
            ulonglong2 wv = *(const ulonglong2*)&ssc[i * 128 + j];
            FMA2(acc0, fv, wv.x, acc0);
            FMA2(acc1, fv, wv.y, acc1);
        }
        if (p < N) {
            float x0, x1, x2, x3;
            unpack2(acc0, x0, x1);
            unpack2(acc1, x2, x3);
            *(float4*)&out[(size_t)p * 128 + j] =
                make_float4(lrelu(x0), lrelu(x1), lrelu(x2), lrelu(x3));
        }
    }
}

// ============================================================================
// launch
// ============================================================================
extern "C" void kernel_launch(void* const* d_in, const int* in_sizes, int n_in,
                              void* d_out, int out_size)
{
    const float* xyz   = (const float*)d_in[0];
    const float* feats = (const float*)d_in[1];
    const int*   nei   = (const int*)  d_in[2];
    const float* pw1 = (const float*)d_in[3];
    const float* pb1 = (const float*)d_in[4];
    const float* pw2 = (const float*)d_in[5];
    const float* pb2 = (const float*)d_in[6];
    const float* u1w = (const float*)d_in[7];
    const float* u1b = (const float*)d_in[8];
    const float* ww1 = (const float*)d_in[9];
    const float* wb1 = (const float*)d_in[10];
    const float* ww2 = (const float*)d_in[11];
    const float* wb2 = (const float*)d_in[12];
    const float* ww3 = (const float*)d_in[13];
    const float* wb3 = (const float*)d_in[14];
    const float* lw  = (const float*)d_in[15];
    const float* lb  = (const float*)d_in[16];
    const float* u2w = (const float*)d_in[17];
    const float* u2b = (const float*)d_in[18];
    const float* scw = (const float*)d_in[19];
    const float* scb = (const float*)d_in[20];

    int N = in_sizes[0] / 3;
    if (N > NMAX) N = NMAX;

    float* out = (float*)d_out;
    long long need = (long long)N * 128 + (long long)N * 48;
    int writeLoc = ((long long)out_size >= need) ? 1 : 0;
    float* loc_out = out + (size_t)N * 128;

    k1_unary1<<<(N + 3) / 4, 128>>>(feats, u1w, u1b, N);
    k2_point<<<N, 128>>>(xyz, nei, pw1, pb1, pw2, pb2,
                         ww1, wb1, ww2, wb2, ww3, wb3,
                         loc_out, N, writeLoc);
    k3_lin<<<(N + 63) / 64, 256>>>(lw, lb, N);

    int smem_k4 = (8192 + 8192 + 4096 + 4096 + 128) * 4;  // 98816 B
    cudaFuncSetAttribute(k4_final, cudaFuncAttributeMaxDynamicSharedMemorySize, smem_k4);
    k4_final<<<(N + 31) / 32, 256, smem_k4>>>(feats, u2w, u2b, scw, scb, out, N);
}

// round 4
// speedup vs baseline: 1.2280x; 1.2280x over previous
#include <cuda_runtime.h>

// ---------------- constants ----------------
#define NMAX   100000
#define CIN    64
#define CMID   32
#define KN     16
#define WNOUT  16
#define COUT   128

// ---------------- scratch ----------------
__device__ float g_feats32[NMAX * CMID];                 // 12.8 MB
__device__ float g_agg[(size_t)NMAX * 1024];             // 409.6 MB
__device__ float g_x[(size_t)NMAX * 64];                 // 25.6 MB

__device__ __forceinline__ float lrelu(float v) { return v > 0.f ? v : 0.1f * v; }

#define FMA2(d, a, b, c) \
    asm("fma.rn.f32x2 %0, %1, %2, %3;" : "=l"(d) : "l"(a), "l"(b), "l"(c))

__device__ __forceinline__ unsigned long long pack2(float lo, float hi) {
    unsigned long long r;
    asm("mov.b64 %0, {%1, %2};" : "=l"(r) : "f"(lo), "f"(hi));
    return r;
}
__device__ __forceinline__ void unpack2(unsigned long long v, float& lo, float& hi) {
    asm("mov.b64 {%0, %1}, %2;" : "=f"(lo), "=f"(hi) : "l"(v));
}

// ============================================================================
// K1: feats32 = dense_feats @ u1_w + u1_b
// ============================================================================
__global__ __launch_bounds__(128) void k1_unary1(
    const float* __restrict__ feats, const float* __restrict__ u1w,
    const float* __restrict__ u1b, int N)
{
    __shared__ float su[CIN * CMID];
    __shared__ float sf[4 * CIN];
    int t = threadIdx.x;
    int p0 = blockIdx.x * 4;
    for (int i = t; i < CIN * CMID; i += 128) su[i] = u1w[i];
#pragma unroll
    for (int q = 0; q < 2; q++) {
        int idx = q * 128 + t;
        int pl = idx >> 6, i = idx & 63;
        int p = p0 + pl;
        sf[idx] = (p < N) ? feats[p * CIN + i] : 0.f;
    }
    __syncthreads();
    int pl = t >> 5, c = t & 31;
    int p = p0 + pl;
    float acc = u1b[c];
#pragma unroll
    for (int i = 0; i < CIN; i++) acc += sf[pl * CIN + i] * su[i * CMID + c];
    if (p < N) g_feats32[p * CMID + c] = acc;
}

// ============================================================================
// K2: 4 points per 128-thread block: localized, pe MLP, weightnet, gather, agg
// ============================================================================
__global__ __launch_bounds__(128) void k2_point(
    const float* __restrict__ xyz, const int* __restrict__ nei,
    const float* __restrict__ pw1, const float* __restrict__ pb1,
    const float* __restrict__ pw2, const float* __restrict__ pb2,
    const float* __restrict__ ww1, const float* __restrict__ wb1,
    const float* __restrict__ ww2, const float* __restrict__ wb2,
    const float* __restrict__ ww3, const float* __restrict__ wb3,
    float* __restrict__ loc_out, int N, int writeLoc)
{
    __shared__ float s_pw1[96], s_pb1[32];
    __shared__ __align__(16) float s_pw2[1024];
    __shared__ float s_pb2[32];
    __shared__ float s_ww1[24], s_wb1[8], s_ww2[64], s_wb2[8], s_ww3[128], s_wb3[16];
    __shared__ float s_loc[4][48];
    __shared__ __align__(16) float s_gf[4][512];    // [k][c]
    __shared__ float s_ph[4][512];                  // [h][k] transposed
    __shared__ __align__(16) float s_pe[4][512];    // [k][c]
    __shared__ float s_wh1[4][128], s_wh2[4][128];
    __shared__ __align__(16) float s_w[4][256];     // [k][w]
    __shared__ int   s_nei[4][16];
    __shared__ float s_ctr[4][3];

    int p0 = blockIdx.x * 4;
    int t  = threadIdx.x;

    // ---- phase 1: weights + meta ----
    if (t < 96) s_pw1[t] = pw1[t];
    if (t < 32) { s_pb1[t] = pb1[t]; s_pb2[t] = pb2[t]; }
#pragma unroll
    for (int q = 0; q < 8; q++) s_pw2[q * 128 + t] = pw2[q * 128 + t];
    if (t < 24) s_ww1[t] = ww1[t];
    if (t >= 24 && t < 32) s_wb1[t - 24] = wb1[t - 24];
    if (t >= 32 && t < 96) s_ww2[t - 32] = ww2[t - 32];
    if (t >= 96 && t < 104) s_wb2[t - 96] = wb2[t - 96];
    s_ww3[t] = ww3[t];
    if (t >= 104 && t < 120) s_wb3[t - 104] = wb3[t - 104];
    if (t < 64) {
        int p = t >> 4, k = t & 15;
        s_nei[p][k] = (p0 + p < N) ? nei[(p0 + p) * KN + k] : 0;
    }
    if (t >= 64 && t < 76) {
        int i = t - 64, p = i / 3, d = i % 3;
        s_ctr[p][d] = (p0 + p < N) ? xyz[(p0 + p) * 3 + d] : 0.f;
    }
    __syncthreads();

    // ---- phase 2: localized + gather feats32 ----
#pragma unroll
    for (int q = 0; q < 2; q++) {
        int i = q * 128 + t;
        if (i < 192) {
            int p = i / 48, r = i - p * 48;
            int k = r / 3, d = r - k * 3;
            float v = xyz[s_nei[p][k] * 3 + d] - s_ctr[p][d];
            s_loc[p][r] = v;
            if (writeLoc && (p0 + p) < N) loc_out[(size_t)(p0 + p) * 48 + r] = v;
        }
    }
#pragma unroll
    for (int q = 0; q < 4; q++) {
        int idx = q * 128 + t;                 // 512 float4 slots
        int p = idx >> 7, rem = idx & 127;
        int k = rem >> 3, c4 = (rem & 7) * 4;
        *(float4*)&s_gf[p][k * 32 + c4] =
            *(const float4*)&g_feats32[(size_t)s_nei[p][k] * CMID + c4];
    }
    __syncthreads();

    // ---- phase 3: pe hidden (transposed [h][k]) + wn hidden1 ----
    {
        int k = t & 15, hb = t >> 4;
#pragma unroll
        for (int p = 0; p < 4; p++) {
            float l0 = s_loc[p][k * 3], l1 = s_loc[p][k * 3 + 1], l2 = s_loc[p][k * 3 + 2];
#pragma unroll
            for (int q = 0; q < 4; q++) {
                int h = hb + q * 8;
                float a = s_pb1[h] + l0 * s_pw1[h] + l1 * s_pw1[32 + h] + l2 * s_pw1[64 + h];
                s_ph[p][h * 16 + k] = lrelu(a);
            }
        }
        int kk = t >> 3, hh = t & 7;
#pragma unroll
        for (int p = 0; p < 4; p++) {
            float m0 = s_loc[p][kk * 3], m1 = s_loc[p][kk * 3 + 1], m2 = s_loc[p][kk * 3 + 2];
            float a = s_wb1[hh] + m0 * s_ww1[hh] + m1 * s_ww1[8 + hh] + m2 * s_ww1[16 + hh];
            s_wh1[p][kk * 8 + hh] = lrelu(a);
        }
    }
    __syncthreads();

    // ---- phase 4: pe out (f32x2) + wn hidden2 ----
    {
#pragma unroll
        for (int q = 0; q < 2; q++) {
            int slot = q * 128 + t;            // 256 slots: (k, cpair)
            int k = slot >> 4, cp = slot & 15;
            int c0 = cp * 2;
            unsigned long long bias = pack2(s_pb2[c0], s_pb2[c0 + 1]);
            unsigned long long wreg[32];
#pragma unroll
            for (int h = 0; h < 32; h++)
                wreg[h] = *(const unsigned long long*)&s_pw2[h * 32 + c0];
#pragma unroll
            for (int p = 0; p < 4; p++) {
                unsigned long long a = bias;
#pragma unroll
                for (int h = 0; h < 32; h++) {
                    float pv = s_ph[p][h * 16 + k];
                    unsigned long long ps = pack2(pv, pv);
                    FMA2(a, ps, wreg[h], a);
                }
                float x0, x1; unpack2(a, x0, x1);
                s_pe[p][k * 32 + c0]     = lrelu(x0);
                s_pe[p][k * 32 + c0 + 1] = lrelu(x1);
            }
        }
        int kk = t >> 3, hh = t & 7;
#pragma unroll
        for (int p = 0; p < 4; p++) {
            float a = s_wb2[hh];
#pragma unroll
            for (int j = 0; j < 8; j++) a += s_wh1[p][kk * 8 + j] * s_ww2[j * 8 + hh];
            s_wh2[p][kk * 8 + hh] = a;
        }
    }
    __syncthreads();

    // ---- phase 5: wn final ----
#pragma unroll
    for (int q = 0; q < 2; q++) {
        int idx = q * 128 + t;
        int k = idx >> 4, wo = idx & 15;
#pragma unroll
        for (int p = 0; p < 4; p++) {
            float a = s_wb3[wo];
#pragma unroll
            for (int j = 0; j < 8; j++) a += s_wh2[p][k * 8 + j] * s_ww3[j * 16 + wo];
            s_w[p][k * 16 + wo] = lrelu(a);
        }
    }
    __syncthreads();

    // ---- phase 6: agg (f32x2), thread: (p,c) slot, 16 w as 8 pairs ----
#pragma unroll
    for (int q = 0; q < 2; q++) {
        int slot = q * 128 + t;                // 256 slots = 4p * 64c
        int p = slot >> 6, c = slot & 63;
        const float* src = (c < 32) ? &s_gf[p][c] : &s_pe[p][c - 32];
        unsigned long long acc[8];
#pragma unroll
        for (int j = 0; j < 8; j++) acc[j] = 0ull;
#pragma unroll
        for (int k = 0; k < KN; k++) {
            float sv = src[k * 32];
            unsigned long long sp = pack2(sv, sv);
            ulonglong2 wa = *(const ulonglong2*)&s_w[p][k * 16];
            ulonglong2 wb = *(const ulonglong2*)&s_w[p][k * 16 + 4];
            ulonglong2 wc = *(const ulonglong2*)&s_w[p][k * 16 + 8];
            ulonglong2 wd = *(const ulonglong2*)&s_w[p][k * 16 + 12];
            FMA2(acc[0], sp, wa.x, acc[0]); FMA2(acc[1], sp, wa.y, acc[1]);
            FMA2(acc[2], sp, wb.x, acc[2]); FMA2(acc[3], sp, wb.y, acc[3]);
            FMA2(acc[4], sp, wc.x, acc[4]); FMA2(acc[5], sp, wc.y, acc[5]);
            FMA2(acc[6], sp, wd.x, acc[6]); FMA2(acc[7], sp, wd.y, acc[7]);
        }
        if (p0 + p < N) {
            float v[16];
#pragma unroll
            for (int j = 0; j < 8; j++) unpack2(acc[j], v[2 * j], v[2 * j + 1]);
            float* dst = &g_agg[(size_t)(p0 + p) * 1024 + c * 16];
            *(float4*)(dst)      = make_float4(v[0], v[1], v[2], v[3]);
            *(float4*)(dst + 4)  = make_float4(v[4], v[5], v[6], v[7]);
            *(float4*)(dst + 8)  = make_float4(v[8], v[9], v[10], v[11]);
            *(float4*)(dst + 12) = make_float4(v[12], v[13], v[14], v[15]);
        }
    }
}

// ============================================================================
// K3: x = leaky(agg @ lin_w + lin_b) — (N x 1024)@(1024 x 64)
// tile: 256 rows x 64 cols, 256 threads, 8x8 per thread, K-chunk 16, reg prefetch
// ============================================================================
__global__ __launch_bounds__(256) void k3_lin(
    const float* __restrict__ lw, const float* __restrict__ lb, int N)
{
    __shared__ __align__(16) float As[16 * 512];   // splat [k][2*row]
    __shared__ __align__(16) float Ws[16 * 64];    // [k][j]
    int t  = threadIdx.x;
    int tb = blockIdx.x * 256;
    int ty = t >> 3, tx = t & 7;
    int r0 = ty * 8, j0 = tx * 8;

    int lrow = tb + t; if (lrow >= N) lrow = N - 1;
    const float* arow = &g_agg[(size_t)lrow * 1024];
    int wk = t >> 4, wj = (t & 15) * 4;

    unsigned long long acc[32];
#pragma unroll
    for (int i = 0; i < 32; i++) acc[i] = 0ull;

    float4 pa0 = *(const float4*)&arow[0];
    float4 pa1 = *(const float4*)&arow[4];
    float4 pa2 = *(const float4*)&arow[8];
    float4 pa3 = *(const float4*)&arow[12];
    float4 pw  = *(const float4*)&lw[(size_t)wk * 64 + wj];

    for (int kt = 0; kt < 64; kt++) {
        __syncthreads();
        {
            float* a0 = &As[2 * t];
            *(unsigned long long*)(a0 + 0 * 512) = pack2(pa0.x, pa0.x);
            *(unsigned long long*)(a0 + 1 * 512) = pack2(pa0.y, pa0.y);
            *(unsigned long long*)(a0 + 2 * 512) = pack2(pa0.z, pa0.z);
            *(unsigned long long*)(a0 + 3 * 512) = pack2(pa0.w, pa0.w);
            *(unsigned long long*)(a0 + 4 * 512) = pack2(pa1.x, pa1.x);
            *(unsigned long long*)(a0 + 5 * 512) = pack2(pa1.y, pa1.y);
            *(unsigned long long*)(a0 + 6 * 512) = pack2(pa1.z, pa1.z);
            *(unsigned long long*)(a0 + 7 * 512) = pack2(pa1.w, pa1.w);
            *(unsigned long long*)(a0 + 8 * 512) = pack2(pa2.x, pa2.x);
            *(unsigned long long*)(a0 + 9 * 512) = pack2(pa2.y, pa2.y);
            *(unsigned long long*)(a0 + 10 * 512) = pack2(pa2.z, pa2.z);
            *(unsigned long long*)(a0 + 11 * 512) = pack2(pa2.w, pa2.w);
            *(unsigned long long*)(a0 + 12 * 512) = pack2(pa3.x, pa3.x);
            *(unsigned long long*)(a0 + 13 * 512) = pack2(pa3.y, pa3.y);
            *(unsigned long long*)(a0 + 14 * 512) = pack2(pa3.z, pa3.z);
            *(unsigned long long*)(a0 + 15 * 512) = pack2(pa3.w, pa3.w);
            *(float4*)&Ws[wk * 64 + wj] = pw;
        }
        __syncthreads();
        if (kt + 1 < 64) {
            int kb = (kt + 1) * 16;
            pa0 = *(const float4*)&arow[kb];
            pa1 = *(const float4*)&arow[kb + 4];
            pa2 = *(const float4*)&arow[kb + 8];
            pa3 = *(const float4*)&arow[kb + 12];
            pw  = *(const float4*)&lw[(size_t)(kb + wk) * 64 + wj];
        }
#pragma unroll
        for (int k = 0; k < 16; k++) {
            ulonglong2 a01 = *(const ulonglong2*)&As[k * 512 + 2 * r0];
            ulonglong2 a23 = *(const ulonglong2*)&As[k * 512 + 2 * r0 + 4];
            ulonglong2 a45 = *(const ulonglong2*)&As[k * 512 + 2 * r0 + 8];
            ulonglong2 a67 = *(const ulonglong2*)&As[k * 512 + 2 * r0 + 12];
            ulonglong2 w01 = *(const ulonglong2*)&Ws[k * 64 + j0];
            ulonglong2 w23 = *(const ulonglong2*)&Ws[k * 64 + j0 + 4];
            FMA2(acc[0],  a01.x, w01.x, acc[0]);  FMA2(acc[1],  a01.x, w01.y, acc[1]);
            FMA2(acc[2],  a01.x, w23.x, acc[2]);  FMA2(acc[3],  a01.x, w23.y, acc[3]);
            FMA2(acc[4],  a01.y, w01.x, acc[4]);  FMA2(acc[5],  a01.y, w01.y, acc[5]);
            FMA2(acc[6],  a01.y, w23.x, acc[6]);  FMA2(acc[7],  a01.y, w23.y, acc[7]);
            FMA2(acc[8],  a23.x, w01.x, acc[8]);  FMA2(acc[9],  a23.x, w01.y, acc[9]);
            FMA2(acc[10], a23.x, w23.x, acc[10]); FMA2(acc[11], a23.x, w23.y, acc[11]);
            FMA2(acc[12], a23.y, w01.x, acc[12]); FMA2(acc[13], a23.y, w01.y, acc[13]);
            FMA2(acc[14], a23.y, w23.x, acc[14]); FMA2(acc[15], a23.y, w23.y, acc[15]);
            FMA2(acc[16], a45.x, w01.x, acc[16]); FMA2(acc[17], a45.x, w01.y, acc[17]);
            FMA2(acc[18], a45.x, w23.x, acc[18]); FMA2(acc[19], a45.x, w23.y, acc[19]);
            FMA2(acc[20], a45.y, w01.x, acc[20]); FMA2(acc[21], a45.y, w01.y, acc[21]);
            FMA2(acc[22], a45.y, w23.x, acc[22]); FMA2(acc[23], a45.y, w23.y, acc[23]);
            FMA2(acc[24], a67.x, w01.x, acc[24]); FMA2(acc[25], a67.x, w01.y, acc[25]);
            FMA2(acc[26], a67.x, w23.x, acc[26]); FMA2(acc[27], a67.x, w23.y, acc[27]);
            FMA2(acc[28], a67.y, w01.x, acc[28]); FMA2(acc[29], a67.y, w01.y, acc[29]);
            FMA2(acc[30], a67.y, w23.x, acc[30]); FMA2(acc[31], a67.y, w23.y, acc[31]);
        }
    }
    float4 b0 = *(const float4*)&lb[j0];
    float4 b1 = *(const float4*)&lb[j0 + 4];
#pragma unroll
    for (int r = 0; r < 8; r++) {
        int row = tb + r0 + r;
        if (row < N) {
            float v[8];
            unpack2(acc[r * 4 + 0], v[0], v[1]);
            unpack2(acc[r * 4 + 1], v[2], v[3]);
            unpack2(acc[r * 4 + 2], v[4], v[5]);
            unpack2(acc[r * 4 + 3], v[6], v[7]);
            float* dst = &g_x[(size_t)row * 64 + j0];
            *(float4*)dst = make_float4(lrelu(v[0] + b0.x), lrelu(v[1] + b0.y),
                                        lrelu(v[2] + b0.z), lrelu(v[3] + b0.w));
            *(float4*)(dst + 4) = make_float4(lrelu(v[4] + b1.x), lrelu(v[5] + b1.y),
                                              lrelu(v[6] + b1.z), lrelu(v[7] + b1.w));
        }
    }
}

// ============================================================================
// K4: out = leaky([x|feats] @ [u2w; scw] + (u2b+scb)) — fused 128->128 GEMM
// tile: 128 rows x 128 cols, 256 threads, 8x8 per thread, K-chunk 16
// W slots: 512 float4 per chunk; slot s -> k = s>>5 (0..15), c4 = (s&31)*4
// ============================================================================
__global__ __launch_bounds__(256) void k4_final(
    const float* __restrict__ feats, const float* __restrict__ u2w,
    const float* __restrict__ u2b, const float* __restrict__ scw,
    const float* __restrict__ scb, float* __restrict__ out, int N)
{
    __shared__ __align__(16) float As[16 * 256];   // splat [k][2*row]
    __shared__ __align__(16) float Ws[16 * 128];   // [k][j]
    __shared__ float sb[128];
    int t  = threadIdx.x;
    int tb = blockIdx.x * 128;
    int ty = t >> 4, tx = t & 15;
    int r0 = ty * 8, j0 = tx * 8;

    int lrow = tb + (t >> 1); if (lrow >= N) lrow = N - 1;
    int ko = (t & 1) * 8;

    if (t < 128) sb[t] = u2b[t] + scb[t];

    unsigned long long acc[32];
#pragma unroll
    for (int i = 0; i < 32; i++) acc[i] = 0ull;

    // prefetch chunk 0 (from g_x)
    const float* asrc = &g_x[(size_t)lrow * 64];
    float4 pa0 = *(const float4*)&asrc[ko];
    float4 pa1 = *(const float4*)&asrc[ko + 4];
    // W slots: thread handles slots t and 256+t
    int wk0 = t >> 5,        wj0 = (t & 31) * 4;   // k rows 0..7
    int wk1 = 8 + (t >> 5),  wj1 = wj0;            // k rows 8..15
    float4 pw0 = *(const float4*)&u2w[(size_t)wk0 * 128 + wj0];
    float4 pw1 = *(const float4*)&u2w[(size_t)wk1 * 128 + wj1];

    for (int ci = 0; ci < 8; ci++) {
        __syncthreads();
        {
            float* a0 = &As[ko * 256 + 2 * (t >> 1)];
            *(unsigned long long*)(a0 + 0 * 256) = pack2(pa0.x, pa0.x);
            *(unsigned long long*)(a0 + 1 * 256) = pack2(pa0.y, pa0.y);
            *(unsigned long long*)(a0 + 2 * 256) = pack2(pa0.z, pa0.z);
            *(unsigned long long*)(a0 + 3 * 256) = pack2(pa0.w, pa0.w);
            *(unsigned long long*)(a0 + 4 * 256) = pack2(pa1.x, pa1.x);
            *(unsigned long long*)(a0 + 5 * 256) = pack2(pa1.y, pa1.y);
            *(unsigned long long*)(a0 + 6 * 256) = pack2(pa1.z, pa1.z);
            *(unsigned long long*)(a0 + 7 * 256) = pack2(pa1.w, pa1.w);
            *(float4*)&Ws[wk0 * 128 + wj0] = pw0;
            *(float4*)&Ws[wk1 * 128 + wj1] = pw1;
        }
        __syncthreads();
        if (ci + 1 < 8) {
            int kb = (ci + 1) * 16;
            const float* a2 = (kb < 64) ? &g_x[(size_t)lrow * 64 + kb]
                                        : &feats[(size_t)lrow * 64 + (kb - 64)];
            pa0 = *(const float4*)&a2[ko];
            pa1 = *(const float4*)&a2[ko + 4];
            const float* w2 = (kb < 64) ? &u2w[(size_t)kb * 128] : &scw[(size_t)(kb - 64) * 128];
            pw0 = *(const float4*)&w2[(size_t)wk0 * 128 + wj0];
            pw1 = *(const float4*)&w2[(size_t)wk1 * 128 + wj1];
        }
#pragma unroll
        for (int k = 0; k < 16; k++) {
            ulonglong2 a01 = *(const ulonglong2*)&As[k * 256 + 2 * r0];
            ulonglong2 a23 = *(const ulonglong2*)&As[k * 256 + 2 * r0 + 4];
            ulonglong2 a45 = *(const ulonglong2*)&As[k * 256 + 2 * r0 + 8];
            ulonglong2 a67 = *(const ulonglong2*)&As[k * 256 + 2 * r0 + 12];
            ulonglong2 w01 = *(const ulonglong2*)&Ws[k * 128 + j0];
            ulonglong2 w23 = *(const ulonglong2*)&Ws[k * 128 + j0 + 4];
            FMA2(acc[0],  a01.x, w01.x, acc[0]);  FMA2(acc[1],  a01.x, w01.y, acc[1]);
            FMA2(acc[2],  a01.x, w23.x, acc[2]);  FMA2(acc[3],  a01.x, w23.y, acc[3]);
            FMA2(acc[4],  a01.y, w01.x, acc[4]);  FMA2(acc[5],  a01.y, w01.y, acc[5]);
            FMA2(acc[6],  a01.y, w23.x, acc[6]);  FMA2(acc[7],  a01.y, w23.y, acc[7]);
            FMA2(acc[8],  a23.x, w01.x, acc[8]);  FMA2(acc[9],  a23.x, w01.y, acc[9]);
            FMA2(acc[10], a23.x, w23.x, acc[10]); FMA2(acc[11], a23.x, w23.y, acc[11]);
            FMA2(acc[12], a23.y, w01.x, acc[12]); FMA2(acc[13], a23.y, w01.y, acc[13]);
            FMA2(acc[14], a23.y, w23.x, acc[14]); FMA2(acc[15], a23.y, w23.y, acc[15]);
            FMA2(acc[16], a45.x, w01.x, acc[16]); FMA2(acc[17], a45.x, w01.y, acc[17]);
            FMA2(acc[18], a45.x, w23.x, acc[18]); FMA2(acc[19], a45.x, w23.y, acc[19]);
            FMA2(acc[20], a45.y, w01.x, acc[20]); FMA2(acc[21], a45.y, w01.y, acc[21]);
            FMA2(acc[22], a45.y, w23.x, acc[22]); FMA2(acc[23], a45.y, w23.y, acc[23]);
            FMA2(acc[24], a67.x, w01.x, acc[24]); FMA2(acc[25], a67.x, w01.y, acc[25]);
            FMA2(acc[26], a67.x, w23.x, acc[26]); FMA2(acc[27], a67.x, w23.y, acc[27]);
            FMA2(acc[28], a67.y, w01.x, acc[28]); FMA2(acc[29], a67.y, w01.y, acc[29]);
            FMA2(acc[30], a67.y, w23.x, acc[30]); FMA2(acc[31], a67.y, w23.y, acc[31]);
        }
    }
    float4 b0 = *(const float4*)&sb[j0];
    float4 b1 = *(const float4*)&sb[j0 + 4];
#pragma unroll
    for (int r = 0; r < 8; r++) {
        int row = tb + r0 + r;
        if (row < N) {
            float v[8];
            unpack2(acc[r * 4 + 0], v[0], v[1]);
            unpack2(acc[r * 4 + 1], v[2], v[3]);
            unpack2(acc[r * 4 + 2], v[4], v[5]);
            unpack2(acc[r * 4 + 3], v[6], v[7]);
            float* dst = &out[(size_t)row * 128 + j0];
            *(float4*)dst = make_float4(lrelu(v[0] + b0.x), lrelu(v[1] + b0.y),
                                        lrelu(v[2] + b0.z), lrelu(v[3] + b0.w));
            *(float4*)(dst + 4) = make_float4(lrelu(v[4] + b1.x), lrelu(v[5] + b1.y),
                                              lrelu(v[6] + b1.z), lrelu(v[7] + b1.w));
        }
    }
}

// ============================================================================
// launch
// ============================================================================
extern "C" void kernel_launch(void* const* d_in, const int* in_sizes, int n_in,
                              void* d_out, int out_size)
{
    const float* xyz   = (const float*)d_in[0];
    const float* feats = (const float*)d_in[1];
    const int*   nei   = (const int*)  d_in[2];
    const float* pw1 = (const float*)d_in[3];
    const float* pb1 = (const float*)d_in[4];
    const float* pw2 = (const float*)d_in[5];
    const float* pb2 = (const float*)d_in[6];
    const float* u1w = (const float*)d_in[7];
    const float* u1b = (const float*)d_in[8];
    const float* ww1 = (const float*)d_in[9];
    const float* wb1 = (const float*)d_in[10];
    const float* ww2 = (const float*)d_in[11];
    const float* wb2 = (const float*)d_in[12];
    const float* ww3 = (const float*)d_in[13];
    const float* wb3 = (const float*)d_in[14];
    const float* lw  = (const float*)d_in[15];
    const float* lb  = (const float*)d_in[16];
    const float* u2w = (const float*)d_in[17];
    const float* u2b = (const float*)d_in[18];
    const float* scw = (const float*)d_in[19];
    const float* scb = (const float*)d_in[20];

    int N = in_sizes[0] / 3;
    if (N > NMAX) N = NMAX;

    float* out = (float*)d_out;
    long long need = (long long)N * 128 + (long long)N * 48;
    int writeLoc = ((long long)out_size >= need) ? 1 : 0;
    float* loc_out = out + (size_t)N * 128;

    k1_unary1<<<(N + 3) / 4, 128>>>(feats, u1w, u1b, N);
    k2_point<<<(N + 3) / 4, 128>>>(xyz, nei, pw1, pb1, pw2, pb2,
                                   ww1, wb1, ww2, wb2, ww3, wb3,
                                   loc_out, N, writeLoc);
    k3_lin<<<(N + 255) / 256, 256>>>(lw, lb, N);
    k4_final<<<(N + 127) / 128, 256>>>(feats, u2w, u2b, scw, scb, out, N);
}

// round 5
// speedup vs baseline: 1.3527x; 1.1015x over previous
#include <cuda_runtime.h>

// ---------------- constants ----------------
#define NMAX   100000
#define CIN    64
#define CMID   32
#define KN     16
#define WNOUT  16
#define COUT   128

// ---------------- scratch ----------------
__device__ float g_feats32[NMAX * CMID];                 // 12.8 MB
__device__ float g_agg[(size_t)NMAX * 1024];             // 409.6 MB
__device__ float g_x[(size_t)NMAX * 64];                 // 25.6 MB

__device__ __forceinline__ float lrelu(float v) { return v > 0.f ? v : 0.1f * v; }

#define FMA2(d, a, b, c) \
    asm("fma.rn.f32x2 %0, %1, %2, %3;" : "=l"(d) : "l"(a), "l"(b), "l"(c))

__device__ __forceinline__ unsigned long long pack2(float lo, float hi) {
    unsigned long long r;
    asm("mov.b64 %0, {%1, %2};" : "=l"(r) : "f"(lo), "f"(hi));
    return r;
}
__device__ __forceinline__ void unpack2(unsigned long long v, float& lo, float& hi) {
    asm("mov.b64 {%0, %1}, %2;" : "=f"(lo), "=f"(hi) : "l"(v));
}

// ============================================================================
// K1: feats32 = dense_feats @ u1_w + u1_b
// ============================================================================
__global__ __launch_bounds__(128) void k1_unary1(
    const float* __restrict__ feats, const float* __restrict__ u1w,
    const float* __restrict__ u1b, int N)
{
    __shared__ float su[CIN * CMID];
    __shared__ float sf[4 * CIN];
    int t = threadIdx.x;
    int p0 = blockIdx.x * 4;
    for (int i = t; i < CIN * CMID; i += 128) su[i] = u1w[i];
#pragma unroll
    for (int q = 0; q < 2; q++) {
        int idx = q * 128 + t;
        int pl = idx >> 6, i = idx & 63;
        int p = p0 + pl;
        sf[idx] = (p < N) ? feats[p * CIN + i] : 0.f;
    }
    __syncthreads();
    int pl = t >> 5, c = t & 31;
    int p = p0 + pl;
    float acc = u1b[c];
#pragma unroll
    for (int i = 0; i < CIN; i++) acc += sf[pl * CIN + i] * su[i * CMID + c];
    if (p < N) g_feats32[p * CMID + c] = acc;
}

// ============================================================================
// K2: 4 points per 128-thread block (unchanged, known-good)
// ============================================================================
__global__ __launch_bounds__(128) void k2_point(
    const float* __restrict__ xyz, const int* __restrict__ nei,
    const float* __restrict__ pw1, const float* __restrict__ pb1,
    const float* __restrict__ pw2, const float* __restrict__ pb2,
    const float* __restrict__ ww1, const float* __restrict__ wb1,
    const float* __restrict__ ww2, const float* __restrict__ wb2,
    const float* __restrict__ ww3, const float* __restrict__ wb3,
    float* __restrict__ loc_out, int N, int writeLoc)
{
    __shared__ float s_pw1[96], s_pb1[32];
    __shared__ __align__(16) float s_pw2[1024];
    __shared__ float s_pb2[32];
    __shared__ float s_ww1[24], s_wb1[8], s_ww2[64], s_wb2[8], s_ww3[128], s_wb3[16];
    __shared__ float s_loc[4][48];
    __shared__ __align__(16) float s_gf[4][512];    // [k][c]
    __shared__ float s_ph[4][512];                  // [h][k] transposed
    __shared__ __align__(16) float s_pe[4][512];    // [k][c]
    __shared__ float s_wh1[4][128], s_wh2[4][128];
    __shared__ __align__(16) float s_w[4][256];     // [k][w]
    __shared__ int   s_nei[4][16];
    __shared__ float s_ctr[4][3];

    int p0 = blockIdx.x * 4;
    int t  = threadIdx.x;

    // ---- phase 1: weights + meta ----
    if (t < 96) s_pw1[t] = pw1[t];
    if (t < 32) { s_pb1[t] = pb1[t]; s_pb2[t] = pb2[t]; }
#pragma unroll
    for (int q = 0; q < 8; q++) s_pw2[q * 128 + t] = pw2[q * 128 + t];
    if (t < 24) s_ww1[t] = ww1[t];
    if (t >= 24 && t < 32) s_wb1[t - 24] = wb1[t - 24];
    if (t >= 32 && t < 96) s_ww2[t - 32] = ww2[t - 32];
    if (t >= 96 && t < 104) s_wb2[t - 96] = wb2[t - 96];
    s_ww3[t] = ww3[t];
    if (t >= 104 && t < 120) s_wb3[t - 104] = wb3[t - 104];
    if (t < 64) {
        int p = t >> 4, k = t & 15;
        s_nei[p][k] = (p0 + p < N) ? nei[(p0 + p) * KN + k] : 0;
    }
    if (t >= 64 && t < 76) {
        int i = t - 64, p = i / 3, d = i % 3;
        s_ctr[p][d] = (p0 + p < N) ? xyz[(p0 + p) * 3 + d] : 0.f;
    }
    __syncthreads();

    // ---- phase 2: localized + gather feats32 ----
#pragma unroll
    for (int q = 0; q < 2; q++) {
        int i = q * 128 + t;
        if (i < 192) {
            int p = i / 48, r = i - p * 48;
            int k = r / 3, d = r - k * 3;
            float v = xyz[s_nei[p][k] * 3 + d] - s_ctr[p][d];
            s_loc[p][r] = v;
            if (writeLoc && (p0 + p) < N) loc_out[(size_t)(p0 + p) * 48 + r] = v;
        }
    }
#pragma unroll
    for (int q = 0; q < 4; q++) {
        int idx = q * 128 + t;                 // 512 float4 slots
        int p = idx >> 7, rem = idx & 127;
        int k = rem >> 3, c4 = (rem & 7) * 4;
        *(float4*)&s_gf[p][k * 32 + c4] =
            *(const float4*)&g_feats32[(size_t)s_nei[p][k] * CMID + c4];
    }
    __syncthreads();

    // ---- phase 3: pe hidden (transposed [h][k]) + wn hidden1 ----
    {
        int k = t & 15, hb = t >> 4;
#pragma unroll
        for (int p = 0; p < 4; p++) {
            float l0 = s_loc[p][k * 3], l1 = s_loc[p][k * 3 + 1], l2 = s_loc[p][k * 3 + 2];
#pragma unroll
            for (int q = 0; q < 4; q++) {
                int h = hb + q * 8;
                float a = s_pb1[h] + l0 * s_pw1[h] + l1 * s_pw1[32 + h] + l2 * s_pw1[64 + h];
                s_ph[p][h * 16 + k] = lrelu(a);
            }
        }
        int kk = t >> 3, hh = t & 7;
#pragma unroll
        for (int p = 0; p < 4; p++) {
            float m0 = s_loc[p][kk * 3], m1 = s_loc[p][kk * 3 + 1], m2 = s_loc[p][kk * 3 + 2];
            float a = s_wb1[hh] + m0 * s_ww1[hh] + m1 * s_ww1[8 + hh] + m2 * s_ww1[16 + hh];
            s_wh1[p][kk * 8 + hh] = lrelu(a);
        }
    }
    __syncthreads();

    // ---- phase 4: pe out (f32x2) + wn hidden2 ----
    {
#pragma unroll
        for (int q = 0; q < 2; q++) {
            int slot = q * 128 + t;            // 256 slots: (k, cpair)
            int k = slot >> 4, cp = slot & 15;
            int c0 = cp * 2;
            unsigned long long bias = pack2(s_pb2[c0], s_pb2[c0 + 1]);
            unsigned long long wreg[32];
#pragma unroll
            for (int h = 0; h < 32; h++)
                wreg[h] = *(const unsigned long long*)&s_pw2[h * 32 + c0];
#pragma unroll
            for (int p = 0; p < 4; p++) {
                unsigned long long a = bias;
#pragma unroll
                for (int h = 0; h < 32; h++) {
                    float pv = s_ph[p][h * 16 + k];
                    unsigned long long ps = pack2(pv, pv);
                    FMA2(a, ps, wreg[h], a);
                }
                float x0, x1; unpack2(a, x0, x1);
                s_pe[p][k * 32 + c0]     = lrelu(x0);
                s_pe[p][k * 32 + c0 + 1] = lrelu(x1);
            }
        }
        int kk = t >> 3, hh = t & 7;
#pragma unroll
        for (int p = 0; p < 4; p++) {
            float a = s_wb2[hh];
#pragma unroll
            for (int j = 0; j < 8; j++) a += s_wh1[p][kk * 8 + j] * s_ww2[j * 8 + hh];
            s_wh2[p][kk * 8 + hh] = a;
        }
    }
    __syncthreads();

    // ---- phase 5: wn final ----
#pragma unroll
    for (int q = 0; q < 2; q++) {
        int idx = q * 128 + t;
        int k = idx >> 4, wo = idx & 15;
#pragma unroll
        for (int p = 0; p < 4; p++) {
            float a = s_wb3[wo];
#pragma unroll
            for (int j = 0; j < 8; j++) a += s_wh2[p][k * 8 + j] * s_ww3[j * 16 + wo];
            s_w[p][k * 16 + wo] = lrelu(a);
        }
    }
    __syncthreads();

    // ---- phase 6: agg (f32x2) ----
#pragma unroll
    for (int q = 0; q < 2; q++) {
        int slot = q * 128 + t;                // 256 slots = 4p * 64c
        int p = slot >> 6, c = slot & 63;
        const float* src = (c < 32) ? &s_gf[p][c] : &s_pe[p][c - 32];
        unsigned long long acc[8];
#pragma unroll
        for (int j = 0; j < 8; j++) acc[j] = 0ull;
#pragma unroll
        for (int k = 0; k < KN; k++) {
            float sv = src[k * 32];
            unsigned long long sp = pack2(sv, sv);
            ulonglong2 wa = *(const ulonglong2*)&s_w[p][k * 16];
            ulonglong2 wb = *(const ulonglong2*)&s_w[p][k * 16 + 4];
            ulonglong2 wc = *(const ulonglong2*)&s_w[p][k * 16 + 8];
            ulonglong2 wd = *(const ulonglong2*)&s_w[p][k * 16 + 12];
            FMA2(acc[0], sp, wa.x, acc[0]); FMA2(acc[1], sp, wa.y, acc[1]);
            FMA2(acc[2], sp, wb.x, acc[2]); FMA2(acc[3], sp, wb.y, acc[3]);
            FMA2(acc[4], sp, wc.x, acc[4]); FMA2(acc[5], sp, wc.y, acc[5]);
            FMA2(acc[6], sp, wd.x, acc[6]); FMA2(acc[7], sp, wd.y, acc[7]);
        }
        if (p0 + p < N) {
            float v[16];
#pragma unroll
            for (int j = 0; j < 8; j++) unpack2(acc[j], v[2 * j], v[2 * j + 1]);
            float* dst = &g_agg[(size_t)(p0 + p) * 1024 + c * 16];
            *(float4*)(dst)      = make_float4(v[0], v[1], v[2], v[3]);
            *(float4*)(dst + 4)  = make_float4(v[4], v[5], v[6], v[7]);
            *(float4*)(dst + 8)  = make_float4(v[8], v[9], v[10], v[11]);
            *(float4*)(dst + 12) = make_float4(v[12], v[13], v[14], v[15]);
        }
    }
}

// ============================================================================
// K3: x = leaky(agg @ lin_w + lin_b) — (N x 1024)@(1024 x 64)
// 256 rows x 64 cols tile, 8x8/thread, 2 CTAs/SM, conflict-free W layout:
//   Ws row k: [ half0: cols {8t..8t+3} at t*4 | half1: cols {8t+4..8t+7} at 32+t*4 ]
// ============================================================================
__global__ __launch_bounds__(256, 2) void k3_lin(
    const float* __restrict__ lw, const float* __restrict__ lb, int N)
{
    __shared__ __align__(16) float As[16 * 512];   // splat [k][2*row]
    __shared__ __align__(16) float Ws[16 * 64];    // [k][swizzled j]
    int t  = threadIdx.x;
    int tb = blockIdx.x * 256;
    int ty = t >> 3, tx = t & 7;
    int r0 = ty * 8, j0 = tx * 8;

    int lrow = tb + t; if (lrow >= N) lrow = N - 1;
    const float* arow = &g_agg[(size_t)lrow * 1024];
    int wk = t >> 4, wc4 = (t & 15) * 4;
    int wdst = wk * 64 + ((wc4 & 4) ? 32 : 0) + (wc4 >> 3) * 4;

    unsigned long long acc[32];
#pragma unroll
    for (int i = 0; i < 32; i++) acc[i] = 0ull;

    float4 pa0 = *(const float4*)&arow[0];
    float4 pa1 = *(const float4*)&arow[4];
    float4 pa2 = *(const float4*)&arow[8];
    float4 pa3 = *(const float4*)&arow[12];
    float4 pw  = *(const float4*)&lw[(size_t)wk * 64 + wc4];

    for (int kt = 0; kt < 64; kt++) {
        __syncthreads();
        {
            float* a0 = &As[2 * t];
            *(unsigned long long*)(a0 + 0 * 512) = pack2(pa0.x, pa0.x);
            *(unsigned long long*)(a0 + 1 * 512) = pack2(pa0.y, pa0.y);
            *(unsigned long long*)(a0 + 2 * 512) = pack2(pa0.z, pa0.z);
            *(unsigned long long*)(a0 + 3 * 512) = pack2(pa0.w, pa0.w);
            *(unsigned long long*)(a0 + 4 * 512) = pack2(pa1.x, pa1.x);
            *(unsigned long long*)(a0 + 5 * 512) = pack2(pa1.y, pa1.y);
            *(unsigned long long*)(a0 + 6 * 512) = pack2(pa1.z, pa1.z);
            *(unsigned long long*)(a0 + 7 * 512) = pack2(pa1.w, pa1.w);
            *(unsigned long long*)(a0 + 8 * 512) = pack2(pa2.x, pa2.x);
            *(unsigned long long*)(a0 + 9 * 512) = pack2(pa2.y, pa2.y);
            *(unsigned long long*)(a0 + 10 * 512) = pack2(pa2.z, pa2.z);
            *(unsigned long long*)(a0 + 11 * 512) = pack2(pa2.w, pa2.w);
            *(unsigned long long*)(a0 + 12 * 512) = pack2(pa3.x, pa3.x);
            *(unsigned long long*)(a0 + 13 * 512) = pack2(pa3.y, pa3.y);
            *(unsigned long long*)(a0 + 14 * 512) = pack2(pa3.z, pa3.z);
            *(unsigned long long*)(a0 + 15 * 512) = pack2(pa3.w, pa3.w);
            *(float4*)&Ws[wdst] = pw;
        }
        __syncthreads();
        if (kt + 1 < 64) {
            int kb = (kt + 1) * 16;
            pa0 = *(const float4*)&arow[kb];
            pa1 = *(const float4*)&arow[kb + 4];
            pa2 = *(const float4*)&arow[kb + 8];
            pa3 = *(const float4*)&arow[kb + 12];
            pw  = *(const float4*)&lw[(size_t)(kb + wk) * 64 + wc4];
        }
#pragma unroll
        for (int k = 0; k < 16; k++) {
            ulonglong2 a01 = *(const ulonglong2*)&As[k * 512 + 2 * r0];
            ulonglong2 a23 = *(const ulonglong2*)&As[k * 512 + 2 * r0 + 4];
            ulonglong2 a45 = *(const ulonglong2*)&As[k * 512 + 2 * r0 + 8];
            ulonglong2 a67 = *(const ulonglong2*)&As[k * 512 + 2 * r0 + 12];
            ulonglong2 w01 = *(const ulonglong2*)&Ws[k * 64 + tx * 4];
            ulonglong2 w23 = *(const ulonglong2*)&Ws[k * 64 + 32 + tx * 4];
            FMA2(acc[0],  a01.x, w01.x, acc[0]);  FMA2(acc[1],  a01.x, w01.y, acc[1]);
            FMA2(acc[2],  a01.x, w23.x, acc[2]);  FMA2(acc[3],  a01.x, w23.y, acc[3]);
            FMA2(acc[4],  a01.y, w01.x, acc[4]);  FMA2(acc[5],  a01.y, w01.y, acc[5]);
            FMA2(acc[6],  a01.y, w23.x, acc[6]);  FMA2(acc[7],  a01.y, w23.y, acc[7]);
            FMA2(acc[8],  a23.x, w01.x, acc[8]);  FMA2(acc[9],  a23.x, w01.y, acc[9]);
            FMA2(acc[10], a23.x, w23.x, acc[10]); FMA2(acc[11], a23.x, w23.y, acc[11]);
            FMA2(acc[12], a23.y, w01.x, acc[12]); FMA2(acc[13], a23.y, w01.y, acc[13]);
            FMA2(acc[14], a23.y, w23.x, acc[14]); FMA2(acc[15], a23.y, w23.y, acc[15]);
            FMA2(acc[16], a45.x, w01.x, acc[16]); FMA2(acc[17], a45.x, w01.y, acc[17]);
            FMA2(acc[18], a45.x, w23.x, acc[18]); FMA2(acc[19], a45.x, w23.y, acc[19]);
            FMA2(acc[20], a45.y, w01.x, acc[20]); FMA2(acc[21], a45.y, w01.y, acc[21]);
            FMA2(acc[22], a45.y, w23.x, acc[22]); FMA2(acc[23], a45.y, w23.y, acc[23]);
            FMA2(acc[24], a67.x, w01.x, acc[24]); FMA2(acc[25], a67.x, w01.y, acc[25]);
            FMA2(acc[26], a67.x, w23.x, acc[26]); FMA2(acc[27], a67.x, w23.y, acc[27]);
            FMA2(acc[28], a67.y, w01.x, acc[28]); FMA2(acc[29], a67.y, w01.y, acc[29]);
            FMA2(acc[30], a67.y, w23.x, acc[30]); FMA2(acc[31], a67.y, w23.y, acc[31]);
        }
    }
    // col order per thread: j0, j0+1, j0+2, j0+3 (w01) then j0+4..j0+7 (w23)
    float4 b0 = *(const float4*)&lb[j0];
    float4 b1 = *(const float4*)&lb[j0 + 4];
#pragma unroll
    for (int r = 0; r < 8; r++) {
        int row = tb + r0 + r;
        if (row < N) {
            float v[8];
            unpack2(acc[r * 4 + 0], v[0], v[1]);
            unpack2(acc[r * 4 + 1], v[2], v[3]);
            unpack2(acc[r * 4 + 2], v[4], v[5]);
            unpack2(acc[r * 4 + 3], v[6], v[7]);
            float* dst = &g_x[(size_t)row * 64 + j0];
            *(float4*)dst = make_float4(lrelu(v[0] + b0.x), lrelu(v[1] + b0.y),
                                        lrelu(v[2] + b0.z), lrelu(v[3] + b0.w));
            *(float4*)(dst + 4) = make_float4(lrelu(v[4] + b1.x), lrelu(v[5] + b1.y),
                                              lrelu(v[6] + b1.z), lrelu(v[7] + b1.w));
        }
    }
}

// ============================================================================
// K4: out = leaky([x|feats] @ [u2w; scw] + (u2b+scb)) — fused 128->128 GEMM
// 128 rows x 128 cols tile, 8x8/thread, 2 CTAs/SM, conflict-free W layout:
//   Ws row k: [ half0: cols {8t..8t+3} at t*4 | half1: cols {8t+4..8t+7} at 64+t*4 ]
// ============================================================================
__global__ __launch_bounds__(256, 2) void k4_final(
    const float* __restrict__ feats, const float* __restrict__ u2w,
    const float* __restrict__ u2b, const float* __restrict__ scw,
    const float* __restrict__ scb, float* __restrict__ out, int N)
{
    __shared__ __align__(16) float As[16 * 256];   // splat [k][2*row]
    __shared__ __align__(16) float Ws[16 * 128];   // [k][swizzled j]
    __shared__ float sb[128];
    int t  = threadIdx.x;
    int tb = blockIdx.x * 128;
    int ty = t >> 4, tx = t & 15;
    int r0 = ty * 8, j0 = tx * 8;

    int lrow = tb + (t >> 1); if (lrow >= N) lrow = N - 1;
    int ko = (t & 1) * 8;

    if (t < 128) sb[t] = u2b[t] + scb[t];

    unsigned long long acc[32];
#pragma unroll
    for (int i = 0; i < 32; i++) acc[i] = 0ull;

    // prefetch chunk 0 (from g_x)
    const float* asrc = &g_x[(size_t)lrow * 64];
    float4 pa0 = *(const float4*)&asrc[ko];
    float4 pa1 = *(const float4*)&asrc[ko + 4];
    // W slots: thread handles slots t and 256+t (global k rows 0..7 and 8..15)
    int wk0 = t >> 5,        wc4 = (t & 31) * 4;   // c4 in 0..124
    int wk1 = 8 + (t >> 5);
    int woff = ((wc4 & 4) ? 64 : 0) + (wc4 >> 3) * 4;
    float4 pw0 = *(const float4*)&u2w[(size_t)wk0 * 128 + wc4];
    float4 pw1 = *(const float4*)&u2w[(size_t)wk1 * 128 + wc4];

    for (int ci = 0; ci < 8; ci++) {
        __syncthreads();
        {
            float* a0 = &As[ko * 256 + 2 * (t >> 1)];
            *(unsigned long long*)(a0 + 0 * 256) = pack2(pa0.x, pa0.x);
            *(unsigned long long*)(a0 + 1 * 256) = pack2(pa0.y, pa0.y);
            *(unsigned long long*)(a0 + 2 * 256) = pack2(pa0.z, pa0.z);
            *(unsigned long long*)(a0 + 3 * 256) = pack2(pa0.w, pa0.w);
            *(unsigned long long*)(a0 + 4 * 256) = pack2(pa1.x, pa1.x);
            *(unsigned long long*)(a0 + 5 * 256) = pack2(pa1.y, pa1.y);
            *(unsigned long long*)(a0 + 6 * 256) = pack2(pa1.z, pa1.z);
            *(unsigned long long*)(a0 + 7 * 256) = pack2(pa1.w, pa1.w);
            *(float4*)&Ws[wk0 * 128 + woff] = pw0;
            *(float4*)&Ws[wk1 * 128 + woff] = pw1;
        }
        __syncthreads();
        if (ci + 1 < 8) {
            int kb = (ci + 1) * 16;
            const float* a2 = (kb < 64) ? &g_x[(size_t)lrow * 64 + kb]
                                        : &feats[(size_t)lrow * 64 + (kb - 64)];
            pa0 = *(const float4*)&a2[ko];
            pa1 = *(const float4*)&a2[ko + 4];
            const float* w2 = (kb < 64) ? &u2w[(size_t)kb * 128] : &scw[(size_t)(kb - 64) * 128];
            pw0 = *(const float4*)&w2[(size_t)wk0 * 128 + wc4];
            pw1 = *(const float4*)&w2[(size_t)wk1 * 128 + wc4];
        }
#pragma unroll
        for (int k = 0; k < 16; k++) {
            ulonglong2 a01 = *(const ulonglong2*)&As[k * 256 + 2 * r0];
            ulonglong2 a23 = *(const ulonglong2*)&As[k * 256 + 2 * r0 + 4];
            ulonglong2 a45 = *(const ulonglong2*)&As[k * 256 + 2 * r0 + 8];
            ulonglong2 a67 = *(const ulonglong2*)&As[k * 256 + 2 * r0 + 12];
            ulonglong2 w01 = *(const ulonglong2*)&Ws[k * 128 + tx * 4];
            ulonglong2 w23 = *(const ulonglong2*)&Ws[k * 128 + 64 + tx * 4];
            FMA2(acc[0],  a01.x, w01.x, acc[0]);  FMA2(acc[1],  a01.x, w01.y, acc[1]);
            FMA2(acc[2],  a01.x, w23.x, acc[2]);  FMA2(acc[3],  a01.x, w23.y, acc[3]);
            FMA2(acc[4],  a01.y, w01.x, acc[4]);  FMA2(acc[5],  a01.y, w01.y, acc[5]);
            FMA2(acc[6],  a01.y, w23.x, acc[6]);  FMA2(acc[7],  a01.y, w23.y, acc[7]);
            FMA2(acc[8],  a23.x, w01.x, acc[8]);  FMA2(acc[9],  a23.x, w01.y, acc[9]);
            FMA2(acc[10], a23.x, w23.x, acc[10]); FMA2(acc[11], a23.x, w23.y, acc[11]);
            FMA2(acc[12], a23.y, w01.x, acc[12]); FMA2(acc[13], a23.y, w01.y, acc[13]);
            FMA2(acc[14], a23.y, w23.x, acc[14]); FMA2(acc[15], a23.y, w23.y, acc[15]);
            FMA2(acc[16], a45.x, w01.x, acc[16]); FMA2(acc[17], a45.x, w01.y, acc[17]);
            FMA2(acc[18], a45.x, w23.x, acc[18]); FMA2(acc[19], a45.x, w23.y, acc[19]);
            FMA2(acc[20], a45.y, w01.x, acc[20]); FMA2(acc[21], a45.y, w01.y, acc[21]);
            FMA2(acc[22], a45.y, w23.x, acc[22]); FMA2(acc[23], a45.y, w23.y, acc[23]);
            FMA2(acc[24], a67.x, w01.x, acc[24]); FMA2(acc[25], a67.x, w01.y, acc[25]);
            FMA2(acc[26], a67.x, w23.x, acc[26]); FMA2(acc[27], a67.x, w23.y, acc[27]);
            FMA2(acc[28], a67.y, w01.x, acc[28]); FMA2(acc[29], a67.y, w01.y, acc[29]);
            FMA2(acc[30], a67.y, w23.x, acc[30]); FMA2(acc[31], a67.y, w23.y, acc[31]);
        }
    }
    float4 b0 = *(const float4*)&sb[j0];
    float4 b1 = *(const float4*)&sb[j0 + 4];
#pragma unroll
    for (int r = 0; r < 8; r++) {
        int row = tb + r0 + r;
        if (row < N) {
            float v[8];
            unpack2(acc[r * 4 + 0], v[0], v[1]);
            unpack2(acc[r * 4 + 1], v[2], v[3]);
            unpack2(acc[r * 4 + 2], v[4], v[5]);
            unpack2(acc[r * 4 + 3], v[6], v[7]);
            float* dst = &out[(size_t)row * 128 + j0];
            *(float4*)dst = make_float4(lrelu(v[0] + b0.x), lrelu(v[1] + b0.y),
                                        lrelu(v[2] + b0.z), lrelu(v[3] + b0.w));
            *(float4*)(dst + 4) = make_float4(lrelu(v[4] + b1.x), lrelu(v[5] + b1.y),
                                              lrelu(v[6] + b1.z), lrelu(v[7] + b1.w));
        }
    }
}

// ============================================================================
// launch
// ============================================================================
extern "C" void kernel_launch(void* const* d_in, const int* in_sizes, int n_in,
                              void* d_out, int out_size)
{
    const float* xyz   = (const float*)d_in[0];
    const float* feats = (const float*)d_in[1];
    const int*   nei   = (const int*)  d_in[2];
    const float* pw1 = (const float*)d_in[3];
    const float* pb1 = (const float*)d_in[4];
    const float* pw2 = (const float*)d_in[5];
    const float* pb2 = (const float*)d_in[6];
    const float* u1w = (const float*)d_in[7];
    const float* u1b = (const float*)d_in[8];
    const float* ww1 = (const float*)d_in[9];
    const float* wb1 = (const float*)d_in[10];
    const float* ww2 = (const float*)d_in[11];
    const float* wb2 = (const float*)d_in[12];
    const float* ww3 = (const float*)d_in[13];
    const float* wb3 = (const float*)d_in[14];
    const float* lw  = (const float*)d_in[15];
    const float* lb  = (const float*)d_in[16];
    const float* u2w = (const float*)d_in[17];
    const float* u2b = (const float*)d_in[18];
    const float* scw = (const float*)d_in[19];
    const float* scb = (const float*)d_in[20];

    int N = in_sizes[0] / 3;
    if (N > NMAX) N = NMAX;

    float* out = (float*)d_out;
    long long need = (long long)N * 128 + (long long)N * 48;
    int writeLoc = ((long long)out_size >= need) ? 1 : 0;
    float* loc_out = out + (size_t)N * 128;

    k1_unary1<<<(N + 3) / 4, 128>>>(feats, u1w, u1b, N);
    k2_point<<<(N + 3) / 4, 128>>>(xyz, nei, pw1, pb1, pw2, pb2,
                                   ww1, wb1, ww2, wb2, ww3, wb3,
                                   loc_out, N, writeLoc);
    k3_lin<<<(N + 255) / 256, 256>>>(lw, lb, N);
    k4_final<<<(N + 127) / 128, 256>>>(feats, u2w, u2b, scw, scb, out, N);
}